// round 10
// baseline (speedup 1.0000x reference)
#include <cuda_runtime.h>
#include <cuda_bf16.h>
#include <math.h>
#include <stdint.h>

#define HID   256
#define NB    128
#define HW    32
#define NBLK  144            // 9 kgrp x 16 j-slices, persistent (1/SM)
#define THREADS 256          // 8 warps
#define PITCH 528            // bytes per bf16 tile row (264 bf16; conflict-free ldmatrix)

// ---- smem layout (bytes) ----
#define SM_CONST 0                              // bias[64], wih[64] floats
#define SM_A_HI  1024                           // A hi: up to 128 x 264 bf16
#define SM_A_LO  (SM_A_HI + 128 * PITCH)
#define SM_W_HI  (SM_A_LO + 128 * PITCH)        // W hi: 64 x 264 bf16, rows n = jt*4+type
#define SM_W_LO  (SM_W_HI + 64 * PITCH)
#define SMEM_TOTAL (SM_W_LO + 64 * PITCH)       // 203776 B

// Cell state s, layout [cell][b][j]. 134 MB scratch.
__device__ float g_s[(size_t)HW * HW * NB * HID];
__device__ int      g_bar_count;
__device__ unsigned g_bar_gen;

__device__ __forceinline__ uint32_t smem_u32(const void* p) {
    uint32_t a;
    asm("{ .reg .u64 t; cvta.to.shared.u64 t, %1; cvt.u32.u64 %0, t; }" : "=r"(a) : "l"(p));
    return a;
}
__device__ __forceinline__ float sigmoidf_(float v) { return 1.0f / (1.0f + expf(-v)); }

__device__ __forceinline__ void ldm_x4(uint32_t& r0, uint32_t& r1, uint32_t& r2, uint32_t& r3,
                                       uint32_t addr) {
    asm volatile("ldmatrix.sync.aligned.m8n8.x4.shared.b16 {%0,%1,%2,%3}, [%4];"
        : "=r"(r0), "=r"(r1), "=r"(r2), "=r"(r3) : "r"(addr));
}
__device__ __forceinline__ void ldm_x2(uint32_t& r0, uint32_t& r1, uint32_t addr) {
    asm volatile("ldmatrix.sync.aligned.m8n8.x2.shared.b16 {%0,%1}, [%2];"
        : "=r"(r0), "=r"(r1) : "r"(addr));
}
__device__ __forceinline__ void mma_bf16(float* c, const uint32_t* a, uint32_t b0, uint32_t b1) {
    asm volatile(
        "mma.sync.aligned.m16n8k16.row.col.f32.bf16.bf16.f32 "
        "{%0,%1,%2,%3}, {%4,%5,%6,%7}, {%8,%9}, {%0,%1,%2,%3};"
        : "+f"(c[0]), "+f"(c[1]), "+f"(c[2]), "+f"(c[3])
        : "r"(a[0]), "r"(a[1]), "r"(a[2]), "r"(a[3]), "r"(b0), "r"(b1));
}

__device__ __forceinline__ uint32_t bf2u(__nv_bfloat162 v) {
    return *reinterpret_cast<uint32_t*>(&v);
}
__device__ __forceinline__ void split2(float a, float b, uint32_t& hi, uint32_t& lo) {
    __nv_bfloat162 h = __floats2bfloat162_rn(a, b);
    float la = a - __low2float(h);
    float lb = b - __high2float(h);
    __nv_bfloat162 l = __floats2bfloat162_rn(la, lb);
    hi = bf2u(h); lo = bf2u(l);
}

__device__ __forceinline__ void grid_barrier() {
    __syncthreads();
    if (threadIdx.x == 0) {
        __threadfence();
        unsigned gen = *((volatile unsigned*)&g_bar_gen);
        int t = atomicAdd(&g_bar_count, 1);
        if (t == NBLK - 1) {
            g_bar_count = 0;
            __threadfence();
            atomicAdd(&g_bar_gen, 1u);
        } else {
            while (*((volatile unsigned*)&g_bar_gen) == gen) { }
        }
    }
    __syncthreads();
}

// One diagonal at M-split M. Block tile: (128/M batches) x 64 gate rows x K=256.
// 8 warps: warps-along-M = 8/M, n8-groups per warp G = 8/M, warps-along-N = M.
template<int M>
__device__ __forceinline__ void run_diag(
    unsigned char* smem, uint32_t smb,
    const float* __restrict__ x, float* __restrict__ out,
    int n_d, int r0, int sb, int kgrp)
{
    constexpr int G    = 8 / M;     // n8-groups per warp (== warps along M)
    constexpr int R    = 128 / M;   // A rows per chunk
    constexpr int TPR  = 2 * M;     // staging threads per row
    constexpr int BN   = (G >= 2) ? 2 * G : 2;

    const int tid  = threadIdx.x;
    const int lane = tid & 31;
    const int wrp  = tid >> 5;
    const int mrow = wrp % G;
    const int nseg = wrp / G;

    const uint32_t a_off = (uint32_t)(mrow * 16 + (lane & 15)) * PITCH + (lane >> 4) * 16;
    uint32_t b_off;
    if (G >= 2) b_off = (uint32_t)(nseg * (64 / M) + (lane & 15)) * PITCH + (lane >> 4) * 16;
    else        b_off = (uint32_t)(nseg * 8 + (lane & 7)) * PITCH + ((lane >> 3) & 1) * 16;

    const int q  = lane & 3;
    const int rr = lane >> 2;
    const int p  = q & 1;
    const float* sbias = (const float*)(smem + SM_CONST);
    const float* swih  = sbias + 64;

    const int tasks = n_d * M;
    for (int u = kgrp; u < tasks; u += 9) {
        const int chunk = u % M;
        const int cell  = u / M;
        const int r = r0 + cell, c = (r0 + cell == r) ? 0 : 0;  // placeholder
        const int rI = r0 + cell;
        const int cI = (2 * 0) + 0;  // computed below properly
        (void)r; (void)c; (void)cI;
        const int rr_cell = rI;
        const int cc_cell = ( ( ( (0) ) ) );
        (void)rr_cell; (void)cc_cell;

        const int row = r0 + cell;
        const int col = ( ( (row) , 0 ) );
        (void)col;
        const int d_sum = 0; (void)d_sum;

        // (clean computation)
        const int rcell = r0 + cell;
        const int ccell = (n_d + r0 - 1) - rcell + ((r0 > 0) ? 0 : 0);
        // d = r + c; for ascending diagonals r0=0, d = n_d-1; descending r0=d-31.
        // Unified: d = r0 + (n_d - 1) when r0==0 ? no. Pass d implicitly: c = d - r.
        // We reconstruct d from r0,n_d: if r0==0 then d=n_d-1 else d = r0 + HW - 1.
        const int dd = (r0 == 0) ? (n_d - 1) : (r0 + HW - 1);
        const int cellc = dd - rcell;
        (void)ccell;

        const int cell_id = rcell * HW + cellc;
        const bool has_up = (rcell > 0), has_left = (cellc > 0);

        float acc[G][4];
        #pragma unroll
        for (int f = 0; f < G; f++)
            #pragma unroll
            for (int e = 0; e < 4; e++) acc[f][e] = 0.0f;

        if (has_up || has_left) {
            // ---- stage hsum for this chunk's R rows, split -> smem A hi/lo ----
            {
                const int bb = tid / TPR;
                const int j0 = (tid % TPR) * (128 / M);
                const int bglob = chunk * R + bb;
                const float* pu = out + (size_t)bglob * (HW * HW * HID)
                                      + (size_t)(cell_id - HW) * HID + j0;
                const float* pl = out + (size_t)bglob * (HW * HW * HID)
                                      + (size_t)(cell_id - 1) * HID + j0;
                unsigned char* ahi = smem + SM_A_HI + bb * PITCH + j0 * 2;
                unsigned char* alo = smem + SM_A_LO + bb * PITCH + j0 * 2;
                #pragma unroll 8
                for (int i = 0; i < 32 / M; i++) {
                    float4 v = make_float4(0.f, 0.f, 0.f, 0.f);
                    if (has_up) {
                        float4 u4 = *(const float4*)(pu + i * 4);
                        v.x = u4.x; v.y = u4.y; v.z = u4.z; v.w = u4.w;
                    }
                    if (has_left) {
                        float4 l4 = *(const float4*)(pl + i * 4);
                        v.x += l4.x; v.y += l4.y; v.z += l4.z; v.w += l4.w;
                    }
                    uint32_t h0, l0, h1, l1;
                    split2(v.x, v.y, h0, l0);
                    split2(v.z, v.w, h1, l1);
                    *(uint2*)(ahi + i * 8) = make_uint2(h0, h1);
                    *(uint2*)(alo + i * 8) = make_uint2(l0, l1);
                }
            }
            __syncthreads();

            // ---- GEMM, frag double-buffered over 16 k-steps ----
            uint32_t ah[2][4], al[2][4], bh[2][BN], bl[2][BN];

            // load kk=0
            ldm_x4(ah[0][0], ah[0][1], ah[0][2], ah[0][3], smb + SM_A_HI + a_off);
            ldm_x4(al[0][0], al[0][1], al[0][2], al[0][3], smb + SM_A_LO + a_off);
            if (G >= 2) {
                #pragma unroll
                for (int jj = 0; jj < G / 2; jj++) {
                    ldm_x4(bh[0][4*jj], bh[0][4*jj+1], bh[0][4*jj+2], bh[0][4*jj+3],
                           smb + SM_W_HI + (uint32_t)(jj * 16) * PITCH + b_off);
                    ldm_x4(bl[0][4*jj], bl[0][4*jj+1], bl[0][4*jj+2], bl[0][4*jj+3],
                           smb + SM_W_LO + (uint32_t)(jj * 16) * PITCH + b_off);
                }
            } else {
                ldm_x2(bh[0][0], bh[0][1], smb + SM_W_HI + b_off);
                ldm_x2(bl[0][0], bl[0][1], smb + SM_W_LO + b_off);
            }

            #pragma unroll
            for (int kk = 0; kk < 16; kk++) {
                const int cur = kk & 1, nxt = cur ^ 1;
                if (kk < 15) {
                    const uint32_t ka = (uint32_t)(kk + 1) * 32;
                    ldm_x4(ah[nxt][0], ah[nxt][1], ah[nxt][2], ah[nxt][3],
                           smb + SM_A_HI + a_off + ka);
                    ldm_x4(al[nxt][0], al[nxt][1], al[nxt][2], al[nxt][3],
                           smb + SM_A_LO + a_off + ka);
                    if (G >= 2) {
                        #pragma unroll
                        for (int jj = 0; jj < G / 2; jj++) {
                            ldm_x4(bh[nxt][4*jj], bh[nxt][4*jj+1], bh[nxt][4*jj+2], bh[nxt][4*jj+3],
                                   smb + SM_W_HI + (uint32_t)(jj * 16) * PITCH + b_off + ka);
                            ldm_x4(bl[nxt][4*jj], bl[nxt][4*jj+1], bl[nxt][4*jj+2], bl[nxt][4*jj+3],
                                   smb + SM_W_LO + (uint32_t)(jj * 16) * PITCH + b_off + ka);
                        }
                    } else {
                        ldm_x2(bh[nxt][0], bh[nxt][1], smb + SM_W_HI + b_off + ka);
                        ldm_x2(bl[nxt][0], bl[nxt][1], smb + SM_W_LO + b_off + ka);
                    }
                }
                #pragma unroll
                for (int g = 0; g < G; g++) {
                    uint32_t f0h, f1h, f0l, f1l;
                    if (G >= 2) {
                        f0h = bh[cur][4*(g>>1) + (g&1)];
                        f1h = bh[cur][4*(g>>1) + 2 + (g&1)];
                        f0l = bl[cur][4*(g>>1) + (g&1)];
                        f1l = bl[cur][4*(g>>1) + 2 + (g&1)];
                    } else {
                        f0h = bh[cur][0]; f1h = bh[cur][1];
                        f0l = bl[cur][0]; f1l = bl[cur][1];
                    }
                    mma_bf16(acc[g], ah[cur], f0h, f1h);
                    mma_bf16(acc[g], ah[cur], f0l, f1l);
                    mma_bf16(acc[g], al[cur], f0h, f1h);
                }
            }
        }

        // ---- epilogue: pair (q, q^1) shares jt; bfly reunites 4 gate types ----
        const size_t s_cur  = (size_t)cell_id * NB * HID;
        const size_t s_up   = (size_t)(cell_id - HW) * NB * HID;
        const size_t s_left = (size_t)(cell_id - 1) * NB * HID;
        const int b_ep = chunk * R + mrow * 16 + rr + p * 8;
        const float xp = x[b_ep * (HW * HW) + cell_id];

        #pragma unroll
        for (int g = 0; g < G; g++) {
            const int gg = nseg * G + g;
            const int jt = gg * 2 + (q >> 1);
            const int j  = sb * 16 + jt;

            const float send0 = p ? acc[g][0] : acc[g][2];
            const float send1 = p ? acc[g][1] : acc[g][3];
            const float recv0 = __shfl_xor_sync(0xFFFFFFFFu, send0, 1);
            const float recv1 = __shfl_xor_sync(0xFFFFFFFFu, send1, 1);

            const float gi = p ? recv0     : acc[g][0];
            const float gf = p ? recv1     : acc[g][1];
            const float gg_ = p ? acc[g][2] : recv0;
            const float go = p ? acc[g][3] : recv1;

            const float vi = gi  + sbias[jt]      + xp * swih[jt];
            const float vf = gf  + sbias[16 + jt] + xp * swih[16 + jt];
            const float vg = gg_ + sbias[32 + jt] + xp * swih[32 + jt];
            const float vo = go  + sbias[48 + jt] + xp * swih[48 + jt];

            const float iv = sigmoidf_(vi);
            const float fv = sigmoidf_(vf);
            const float gv = tanhf(vg);
            const float ov = sigmoidf_(vo);

            float ssum = 0.0f;
            if (has_up)   ssum += g_s[s_up   + (size_t)b_ep * HID + j];
            if (has_left) ssum += g_s[s_left + (size_t)b_ep * HID + j];

            const float sv = fv * ssum + iv * gv;
            const float hv = ov * tanhf(sv);

            g_s[s_cur + (size_t)b_ep * HID + j] = sv;
            out[(size_t)b_ep * (HW * HW * HID) + (size_t)cell_id * HID + j] = hv;
        }
        __syncthreads();
    }
}

__global__ __launch_bounds__(THREADS, 1)
void mdlstm_mma(const float* __restrict__ x,
                const float* __restrict__ w_ih,
                const float* __restrict__ w_hh,
                const float* __restrict__ bias,
                float*       __restrict__ out)
{
    extern __shared__ unsigned char smem[];
    const uint32_t smb = smem_u32(smem);
    const int tid  = threadIdx.x;
    const int sb   = blockIdx.x & 15;     // j-slice (W resident per block)
    const int kgrp = blockIdx.x >> 4;     // 0..8

    // ---- one-time: W slice split into smem hi/lo, rows n = jt*4 + type ----
    {
        const int n    = tid >> 2;                 // 0..63
        const int kc   = (tid & 3) * 64;
        const int type = n & 3, jt = n >> 2;
        const int j    = sb * 16 + jt;
        const float* src = w_hh + ((size_t)(type * 256 + j) * 256 + kc);
        unsigned char* dhi = smem + SM_W_HI + n * PITCH + kc * 2;
        unsigned char* dlo = smem + SM_W_LO + n * PITCH + kc * 2;
        #pragma unroll
        for (int i = 0; i < 16; i++) {
            float4 v = *(const float4*)(src + i * 4);
            uint32_t h0, l0, h1, l1;
            split2(v.x, v.y, h0, l0);
            split2(v.z, v.w, h1, l1);
            *(uint2*)(dhi + i * 8) = make_uint2(h0, h1);
            *(uint2*)(dlo + i * 8) = make_uint2(l0, l1);
        }
    }
    if (tid < 64) {
        const int type = tid >> 4, jt = tid & 15;
        const int j = sb * 16 + jt;
        ((float*)(smem + SM_CONST))[tid]      = bias[type * 256 + j];
        ((float*)(smem + SM_CONST))[64 + tid] = w_ih[type * 256 + j];
    }
    __syncthreads();

    for (int d = 0; d < 2 * HW - 1; d++) {
        const int n_d = (d < HW) ? (d + 1) : (2 * HW - 1 - d);
        const int r0  = (d > HW - 1) ? d - (HW - 1) : 0;

        if      (n_d == 1) run_diag<8>(smem, smb, x, out, n_d, r0, sb, kgrp);
        else if (n_d == 2) run_diag<4>(smem, smb, x, out, n_d, r0, sb, kgrp);
        else if (n_d <= 4) run_diag<2>(smem, smb, x, out, n_d, r0, sb, kgrp);
        else               run_diag<1>(smem, smb, x, out, n_d, r0, sb, kgrp);

        grid_barrier();
    }
}

extern "C" void kernel_launch(void* const* d_in, const int* in_sizes, int n_in,
                              void* d_out, int out_size) {
    const float* x    = (const float*)d_in[0];
    const float* w_ih = (const float*)d_in[1];
    const float* w_hh = (const float*)d_in[2];
    const float* bias = (const float*)d_in[3];
    float* out = (float*)d_out;

    cudaFuncSetAttribute(mdlstm_mma,
                         cudaFuncAttributeMaxDynamicSharedMemorySize, SMEM_TOTAL);
    mdlstm_mma<<<NBLK, THREADS, SMEM_TOTAL>>>(x, w_ih, w_hh, bias, out);
}

// round 11
// speedup vs baseline: 1.4104x; 1.4104x over previous
#include <cuda_runtime.h>
#include <cuda_bf16.h>
#include <math.h>
#include <stdint.h>

#define HID   256
#define NB    128
#define HW    32
#define NBLK  144            // 9 cell-slots x 16 j-slices, persistent (1/SM)
#define CSLOTS 9
#define THREADS 256
#define PITCH 528            // bytes per bf16 tile row (264 bf16; ldmatrix conflict-free)

// ---- smem layout (bytes) ----
#define SM_CONST 0                              // bias[64], wih[64] floats (512 B)
#define SM_A_HI  1024                           // A hi: 128 x 264 bf16 (67584 B)
#define SM_A_LO  (SM_A_HI + 128 * PITCH)
#define SM_W_HI  (SM_A_LO + 128 * PITCH)        // W hi: 64 x 264 bf16 (33792 B)
#define SM_W_LO  (SM_W_HI + 64 * PITCH)
#define SMEM_TOTAL (SM_W_LO + 64 * PITCH)       // 203776 B

// Cell state s, layout [cell][b][j]. 134 MB scratch.
__device__ float g_s[(size_t)HW * HW * NB * HID];
// Per-cell completion counters (16 j-slice blocks each).
__device__ int g_cellflag[HW * HW];

__global__ void reset_flags() {
    int i = blockIdx.x * blockDim.x + threadIdx.x;
    if (i < HW * HW) g_cellflag[i] = 0;
}

__device__ __forceinline__ uint32_t smem_u32(const void* p) {
    uint32_t a;
    asm("{ .reg .u64 t; cvta.to.shared.u64 t, %1; cvt.u32.u64 %0, t; }" : "=r"(a) : "l"(p));
    return a;
}
__device__ __forceinline__ float sigmoidf_(float v) { return 1.0f / (1.0f + expf(-v)); }

__device__ __forceinline__ void ldm_x4(uint32_t& r0, uint32_t& r1, uint32_t& r2, uint32_t& r3,
                                       uint32_t addr) {
    asm volatile("ldmatrix.sync.aligned.m8n8.x4.shared.b16 {%0,%1,%2,%3}, [%4];"
        : "=r"(r0), "=r"(r1), "=r"(r2), "=r"(r3) : "r"(addr));
}
__device__ __forceinline__ void mma_bf16(float* c, const uint32_t* a, uint32_t b0, uint32_t b1) {
    asm volatile(
        "mma.sync.aligned.m16n8k16.row.col.f32.bf16.bf16.f32 "
        "{%0,%1,%2,%3}, {%4,%5,%6,%7}, {%8,%9}, {%0,%1,%2,%3};"
        : "+f"(c[0]), "+f"(c[1]), "+f"(c[2]), "+f"(c[3])
        : "r"(a[0]), "r"(a[1]), "r"(a[2]), "r"(a[3]), "r"(b0), "r"(b1));
}

__device__ __forceinline__ uint32_t bf2u(__nv_bfloat162 v) {
    return *reinterpret_cast<uint32_t*>(&v);
}
// split float pair -> (hi bf16x2, lo bf16x2)
__device__ __forceinline__ void split2(float a, float b, uint32_t& hi, uint32_t& lo) {
    __nv_bfloat162 h = __floats2bfloat162_rn(a, b);
    float la = a - __low2float(h);
    float lb = b - __high2float(h);
    __nv_bfloat162 l = __floats2bfloat162_rn(la, lb);
    hi = bf2u(h); lo = bf2u(l);
}

// Persistent MD-LSTM, dataflow-synchronized. Block = 256 threads (8 warps).
// Tile: M=128 batches x N=64 gate rows (n = type*16 + jt; j = sb*16 + jt)
// x K=256, split-precision bf16 HMMA. Per-cell flags replace global barriers.
__global__ __launch_bounds__(THREADS, 1)
void mdlstm_mma(const float* __restrict__ x,
                const float* __restrict__ w_ih,
                const float* __restrict__ w_hh,
                const float* __restrict__ bias,
                float*       __restrict__ out)
{
    extern __shared__ unsigned char smem[];
    const uint32_t smb  = smem_u32(smem);
    const int tid  = threadIdx.x;
    const int lane = tid & 31;
    const int wrp  = tid >> 5;            // 0..7
    const int sb    = blockIdx.x & 15;    // j-slice
    const int cslot = blockIdx.x >> 4;    // 0..8

    // ---- one-time: W slice (64 rows x 256 k) split into smem hi/lo ----
    {
        const int n    = tid >> 2;                 // 0..63
        const int kc   = (tid & 3) * 64;
        const int type = n >> 4, jt = n & 15;
        const int j    = sb * 16 + jt;
        const float* src = w_hh + ((size_t)(type * 256 + j) * 256 + kc);
        unsigned char* dhi = smem + SM_W_HI + n * PITCH + kc * 2;
        unsigned char* dlo = smem + SM_W_LO + n * PITCH + kc * 2;
        #pragma unroll 4
        for (int i = 0; i < 16; i++) {
            float4 v = *(const float4*)(src + i * 4);
            uint32_t h0, l0, h1, l1;
            split2(v.x, v.y, h0, l0);
            split2(v.z, v.w, h1, l1);
            *(uint2*)(dhi + i * 8) = make_uint2(h0, h1);
            *(uint2*)(dlo + i * 8) = make_uint2(l0, l1);
        }
    }
    if (tid < 64) {
        const int type = tid >> 4, jt = tid & 15;
        const int j = sb * 16 + jt;
        ((float*)(smem + SM_CONST))[tid]      = bias[type * 256 + j];
        ((float*)(smem + SM_CONST))[64 + tid] = w_ih[type * 256 + j];
    }
    __syncthreads();

    // per-lane ldmatrix address components
    const int m0 = wrp * 16;
    const uint32_t a_off = (uint32_t)(m0 + (lane & 15)) * PITCH + (lane >> 4) * 16;
    const uint32_t b_off = (uint32_t)(lane & 15) * PITCH + (lane >> 4) * 16;

    const int q  = lane & 3;
    const int g8 = lane >> 2;
    const float* sbias = (const float*)(smem + SM_CONST);
    const float* swih  = sbias + 64;

    for (int d = 0; d < 2 * HW - 1; d++) {
        const int n_d = (d < HW) ? (d + 1) : (2 * HW - 1 - d);
        const int r0  = (d > HW - 1) ? d - (HW - 1) : 0;

        for (int cell = cslot; cell < n_d; cell += CSLOTS) {
            const int r = r0 + cell, c = d - r;
            const int cell_id = r * HW + c;
            const bool has_up = (r > 0), has_left = (c > 0);

            float acc[8][4];
            #pragma unroll
            for (int f = 0; f < 8; f++)
                #pragma unroll
                for (int e = 0; e < 4; e++) acc[f][e] = 0.0f;

            if (has_up || has_left) {
                // ---- dataflow wait: neighbors fully produced (16 slices each) ----
                if (tid == 0) {
                    volatile int* vf = (volatile int*)g_cellflag;
                    if (has_up)   while (vf[cell_id - HW] < 16) { }
                    if (has_left) while (vf[cell_id - 1]  < 16) { }
                }
                __syncthreads();

                // ---- stage hsum = h_up + h_left, split -> smem A hi/lo ----
                {
                    const int bb = tid >> 1;
                    const int j0 = (tid & 1) * 128;
                    const float* pu = out + (size_t)bb * (HW * HW * HID)
                                          + (size_t)(cell_id - HW) * HID + j0;
                    const float* pl = out + (size_t)bb * (HW * HW * HID)
                                          + (size_t)(cell_id - 1) * HID + j0;
                    unsigned char* ahi = smem + SM_A_HI + bb * PITCH + j0 * 2;
                    unsigned char* alo = smem + SM_A_LO + bb * PITCH + j0 * 2;
                    #pragma unroll 8
                    for (int i = 0; i < 32; i++) {
                        float4 v = make_float4(0.f, 0.f, 0.f, 0.f);
                        if (has_up) {
                            float4 u = __ldcg((const float4*)(pu + i * 4));
                            v.x = u.x; v.y = u.y; v.z = u.z; v.w = u.w;
                        }
                        if (has_left) {
                            float4 l = __ldcg((const float4*)(pl + i * 4));
                            v.x += l.x; v.y += l.y; v.z += l.z; v.w += l.w;
                        }
                        uint32_t h0, l0, h1, l1;
                        split2(v.x, v.y, h0, l0);
                        split2(v.z, v.w, h1, l1);
                        *(uint2*)(ahi + i * 8) = make_uint2(h0, h1);
                        *(uint2*)(alo + i * 8) = make_uint2(l0, l1);
                    }
                }
                __syncthreads();

                // ---- GEMM: gates[b][n] = sum_k hsum[b][k] * W[n][k] ----
                #pragma unroll 2
                for (int kk = 0; kk < 16; kk++) {
                    const uint32_t ka = kk * 32;        // 16 bf16 = 32 B per k-step
                    uint32_t ah[4], al[4];
                    ldm_x4(ah[0], ah[1], ah[2], ah[3], smb + SM_A_HI + a_off + ka);
                    ldm_x4(al[0], al[1], al[2], al[3], smb + SM_A_LO + a_off + ka);
                    #pragma unroll
                    for (int g = 0; g < 4; g++) {
                        uint32_t bh0, bh1, bh2, bh3, bl0, bl1, bl2, bl3;
                        ldm_x4(bh0, bh1, bh2, bh3,
                               smb + SM_W_HI + (uint32_t)g * 16 * PITCH + b_off + ka);
                        ldm_x4(bl0, bl1, bl2, bl3,
                               smb + SM_W_LO + (uint32_t)g * 16 * PITCH + b_off + ka);
                        mma_bf16(acc[g * 2],     ah, bh0, bh2);
                        mma_bf16(acc[g * 2 + 1], ah, bh1, bh3);
                        mma_bf16(acc[g * 2],     ah, bl0, bl2);
                        mma_bf16(acc[g * 2 + 1], ah, bl1, bl3);
                        mma_bf16(acc[g * 2],     al, bh0, bh2);
                        mma_bf16(acc[g * 2 + 1], al, bh1, bh3);
                    }
                }
            }

            // ---- epilogue: thread owns (2 b-rows) x (4 jt) x 4 gate types ----
            const size_t s_cur  = (size_t)cell_id * NB * HID;
            const size_t s_up   = (size_t)(cell_id - HW) * NB * HID;
            const size_t s_left = (size_t)(cell_id - 1) * NB * HID;

            #pragma unroll
            for (int h = 0; h < 2; h++) {
                const int b = m0 + g8 + h * 8;
                const float xp = x[b * (HW * HW) + cell_id];
                #pragma unroll
                for (int p = 0; p < 2; p++) {
                    const int jt0 = p * 8 + q * 2;
                    const int j0e = sb * 16 + jt0;

                    float2 ssum = make_float2(0.f, 0.f);
                    if (has_up) {
                        float2 t = __ldcg((const float2*)&g_s[s_up + (size_t)b * HID + j0e]);
                        ssum.x += t.x; ssum.y += t.y;
                    }
                    if (has_left) {
                        float2 t = __ldcg((const float2*)&g_s[s_left + (size_t)b * HID + j0e]);
                        ssum.x += t.x; ssum.y += t.y;
                    }

                    float sv[2], hv[2];
                    #pragma unroll
                    for (int cc = 0; cc < 2; cc++) {
                        const int jt = jt0 + cc;
                        const int e  = h * 2 + cc;
                        const float gi = acc[0 + p][e] + sbias[jt]      + xp * swih[jt];
                        const float gf = acc[2 + p][e] + sbias[16 + jt] + xp * swih[16 + jt];
                        const float gg = acc[4 + p][e] + sbias[32 + jt] + xp * swih[32 + jt];
                        const float go = acc[6 + p][e] + sbias[48 + jt] + xp * swih[48 + jt];

                        const float iv = sigmoidf_(gi);
                        const float fv = sigmoidf_(gf);
                        const float gv = tanhf(gg);
                        const float ov = sigmoidf_(go);

                        const float ss = (cc == 0) ? ssum.x : ssum.y;
                        sv[cc] = fv * ss + iv * gv;
                        hv[cc] = ov * tanhf(sv[cc]);
                    }
                    *(float2*)&g_s[s_cur + (size_t)b * HID + j0e] = make_float2(sv[0], sv[1]);
                    *(float2*)&out[(size_t)b * (HW * HW * HID)
                                   + (size_t)cell_id * HID + j0e]  = make_float2(hv[0], hv[1]);
                }
            }

            // ---- publish: this j-slice of cell_id is complete ----
            __threadfence();
            __syncthreads();           // also protects smem A for next staging
            if (tid == 0) atomicAdd(&g_cellflag[cell_id], 1);
        }
    }
}

extern "C" void kernel_launch(void* const* d_in, const int* in_sizes, int n_in,
                              void* d_out, int out_size) {
    const float* x    = (const float*)d_in[0];
    const float* w_ih = (const float*)d_in[1];
    const float* w_hh = (const float*)d_in[2];
    const float* bias = (const float*)d_in[3];
    float* out = (float*)d_out;

    cudaFuncSetAttribute(mdlstm_mma,
                         cudaFuncAttributeMaxDynamicSharedMemorySize, SMEM_TOTAL);

    reset_flags<<<4, 256>>>();
    mdlstm_mma<<<NBLK, THREADS, SMEM_TOTAL>>>(x, w_ih, w_hh, bias, out);
}

// round 12
// speedup vs baseline: 1.7496x; 1.2405x over previous
#include <cuda_runtime.h>
#include <cuda_bf16.h>
#include <math.h>
#include <stdint.h>

#define HID   256
#define NB    128
#define HW    32
#define NBLK  144            // 9 cell-slots x 16 j-slices, persistent (1/SM)
#define CSLOTS 9
#define THREADS 256
#define PITCH 528            // bytes per bf16 tile row (264 bf16; ldmatrix conflict-free)

// ---- smem layout (bytes) ----
#define SM_CONST 0                              // bias[64], wih[64] floats (512 B)
#define SM_A_HI  1024                           // A hi: 128 x 264 bf16 (67584 B)
#define SM_A_LO  (SM_A_HI + 128 * PITCH)
#define SM_W_HI  (SM_A_LO + 128 * PITCH)        // W hi: 64 x 264 bf16 (33792 B)
#define SM_W_LO  (SM_W_HI + 64 * PITCH)
#define SMEM_TOTAL (SM_W_LO + 64 * PITCH)       // 203776 B

// Cell state s, layout [cell][b][j]. 134 MB scratch.
__device__ float g_s[(size_t)HW * HW * NB * HID];
// grid barrier
__device__ int      g_bar_count;
__device__ unsigned g_bar_gen;

__device__ __forceinline__ uint32_t smem_u32(const void* p) {
    uint32_t a;
    asm("{ .reg .u64 t; cvta.to.shared.u64 t, %1; cvt.u32.u64 %0, t; }" : "=r"(a) : "l"(p));
    return a;
}

// Fast activations: MUFU.EX2 + MUFU.RCP based. rel err ~1e-6.
// sigmoid: e^{-x} overflows to inf for x << 0 -> rcp gives 0 (correct limit).
__device__ __forceinline__ float fsigmoid(float x) {
    return __fdividef(1.0f, 1.0f + __expf(-x));
}
// tanh(x) = 2*sigmoid(2x) - 1; saturates correctly at both tails.
__device__ __forceinline__ float ftanh(float x) {
    return fmaf(2.0f, fsigmoid(2.0f * x), -1.0f);
}

__device__ __forceinline__ void ldm_x4(uint32_t& r0, uint32_t& r1, uint32_t& r2, uint32_t& r3,
                                       uint32_t addr) {
    asm volatile("ldmatrix.sync.aligned.m8n8.x4.shared.b16 {%0,%1,%2,%3}, [%4];"
        : "=r"(r0), "=r"(r1), "=r"(r2), "=r"(r3) : "r"(addr));
}
__device__ __forceinline__ void mma_bf16(float* c, const uint32_t* a, uint32_t b0, uint32_t b1) {
    asm volatile(
        "mma.sync.aligned.m16n8k16.row.col.f32.bf16.bf16.f32 "
        "{%0,%1,%2,%3}, {%4,%5,%6,%7}, {%8,%9}, {%0,%1,%2,%3};"
        : "+f"(c[0]), "+f"(c[1]), "+f"(c[2]), "+f"(c[3])
        : "r"(a[0]), "r"(a[1]), "r"(a[2]), "r"(a[3]), "r"(b0), "r"(b1));
}

__device__ __forceinline__ uint32_t bf2u(__nv_bfloat162 v) {
    return *reinterpret_cast<uint32_t*>(&v);
}
// split float pair -> (hi bf16x2, lo bf16x2)
__device__ __forceinline__ void split2(float a, float b, uint32_t& hi, uint32_t& lo) {
    __nv_bfloat162 h = __floats2bfloat162_rn(a, b);
    float la = a - __low2float(h);
    float lb = b - __high2float(h);
    __nv_bfloat162 l = __floats2bfloat162_rn(la, lb);
    hi = bf2u(h); lo = bf2u(l);
}

__device__ __forceinline__ void grid_barrier() {
    __syncthreads();
    if (threadIdx.x == 0) {
        __threadfence();
        unsigned gen = *((volatile unsigned*)&g_bar_gen);
        int t = atomicAdd(&g_bar_count, 1);
        if (t == NBLK - 1) {
            g_bar_count = 0;
            __threadfence();
            atomicAdd(&g_bar_gen, 1u);
        } else {
            while (*((volatile unsigned*)&g_bar_gen) == gen) { }
        }
    }
    __syncthreads();
}

// Persistent MD-LSTM: one launch walks all 63 anti-diagonals.
// Block = 256 threads (8 warps). Tile: M=128 batches x N=64 gate rows
// (n = type*16 + jt; j = sb*16 + jt) x K=256, split-precision bf16 HMMA.
__global__ __launch_bounds__(THREADS, 1)
void mdlstm_mma(const float* __restrict__ x,
                const float* __restrict__ w_ih,
                const float* __restrict__ w_hh,
                const float* __restrict__ bias,
                float*       __restrict__ out)
{
    extern __shared__ unsigned char smem[];
    const uint32_t smb  = smem_u32(smem);
    const int tid  = threadIdx.x;
    const int lane = tid & 31;
    const int wrp  = tid >> 5;            // 0..7
    const int sb    = blockIdx.x & 15;    // j-slice
    const int cslot = blockIdx.x >> 4;    // 0..8

    // ---- one-time: W slice (64 rows x 256 k) split into smem hi/lo ----
    {
        const int n    = tid >> 2;                 // 0..63
        const int kc   = (tid & 3) * 64;
        const int type = n >> 4, jt = n & 15;
        const int j    = sb * 16 + jt;
        const float* src = w_hh + ((size_t)(type * 256 + j) * 256 + kc);
        unsigned char* dhi = smem + SM_W_HI + n * PITCH + kc * 2;
        unsigned char* dlo = smem + SM_W_LO + n * PITCH + kc * 2;
        #pragma unroll 4
        for (int i = 0; i < 16; i++) {
            float4 v = *(const float4*)(src + i * 4);
            uint32_t h0, l0, h1, l1;
            split2(v.x, v.y, h0, l0);
            split2(v.z, v.w, h1, l1);
            *(uint2*)(dhi + i * 8) = make_uint2(h0, h1);
            *(uint2*)(dlo + i * 8) = make_uint2(l0, l1);
        }
    }
    if (tid < 64) {
        const int type = tid >> 4, jt = tid & 15;
        const int j = sb * 16 + jt;
        ((float*)(smem + SM_CONST))[tid]      = bias[type * 256 + j];
        ((float*)(smem + SM_CONST))[64 + tid] = w_ih[type * 256 + j];
    }
    __syncthreads();

    // per-lane ldmatrix address components
    const int m0 = wrp * 16;
    const uint32_t a_off = (uint32_t)(m0 + (lane & 15)) * PITCH + (lane >> 4) * 16;
    const uint32_t b_off = (uint32_t)(lane & 15) * PITCH + (lane >> 4) * 16;

    const int q  = lane & 3;
    const int g8 = lane >> 2;
    const float* sbias = (const float*)(smem + SM_CONST);
    const float* swih  = sbias + 64;

    for (int d = 0; d < 2 * HW - 1; d++) {
        const int n_d = (d < HW) ? (d + 1) : (2 * HW - 1 - d);
        const int r0  = (d > HW - 1) ? d - (HW - 1) : 0;

        for (int cell = cslot; cell < n_d; cell += CSLOTS) {
            const int r = r0 + cell, c = d - r;
            const int cell_id = r * HW + c;
            const bool has_up = (r > 0), has_left = (c > 0);

            float acc[8][4];
            #pragma unroll
            for (int f = 0; f < 8; f++)
                #pragma unroll
                for (int e = 0; e < 4; e++) acc[f][e] = 0.0f;

            if (has_up || has_left) {
                // ---- stage hsum = h_up + h_left, split -> smem A hi/lo ----
                {
                    const int bb = tid >> 1;
                    const int j0 = (tid & 1) * 128;
                    const float* pu = out + (size_t)bb * (HW * HW * HID)
                                          + (size_t)(cell_id - HW) * HID + j0;
                    const float* pl = out + (size_t)bb * (HW * HW * HID)
                                          + (size_t)(cell_id - 1) * HID + j0;
                    unsigned char* ahi = smem + SM_A_HI + bb * PITCH + j0 * 2;
                    unsigned char* alo = smem + SM_A_LO + bb * PITCH + j0 * 2;
                    #pragma unroll 8
                    for (int i = 0; i < 32; i++) {
                        float4 v = make_float4(0.f, 0.f, 0.f, 0.f);
                        if (has_up) {
                            float4 u = *(const float4*)(pu + i * 4);
                            v.x = u.x; v.y = u.y; v.z = u.z; v.w = u.w;
                        }
                        if (has_left) {
                            float4 l = *(const float4*)(pl + i * 4);
                            v.x += l.x; v.y += l.y; v.z += l.z; v.w += l.w;
                        }
                        uint32_t h0, l0, h1, l1;
                        split2(v.x, v.y, h0, l0);
                        split2(v.z, v.w, h1, l1);
                        *(uint2*)(ahi + i * 8) = make_uint2(h0, h1);
                        *(uint2*)(alo + i * 8) = make_uint2(l0, l1);
                    }
                }
                __syncthreads();

                // ---- GEMM: gates[b][n] = sum_k hsum[b][k] * W[n][k] ----
                #pragma unroll 2
                for (int kk = 0; kk < 16; kk++) {
                    const uint32_t ka = kk * 32;        // 16 bf16 = 32 B per k-step
                    uint32_t ah[4], al[4];
                    ldm_x4(ah[0], ah[1], ah[2], ah[3], smb + SM_A_HI + a_off + ka);
                    ldm_x4(al[0], al[1], al[2], al[3], smb + SM_A_LO + a_off + ka);
                    #pragma unroll
                    for (int g = 0; g < 4; g++) {
                        uint32_t bh0, bh1, bh2, bh3, bl0, bl1, bl2, bl3;
                        ldm_x4(bh0, bh1, bh2, bh3,
                               smb + SM_W_HI + (uint32_t)g * 16 * PITCH + b_off + ka);
                        ldm_x4(bl0, bl1, bl2, bl3,
                               smb + SM_W_LO + (uint32_t)g * 16 * PITCH + b_off + ka);
                        mma_bf16(acc[g * 2],     ah, bh0, bh2);
                        mma_bf16(acc[g * 2 + 1], ah, bh1, bh3);
                        mma_bf16(acc[g * 2],     ah, bl0, bl2);
                        mma_bf16(acc[g * 2 + 1], ah, bl1, bl3);
                        mma_bf16(acc[g * 2],     al, bh0, bh2);
                        mma_bf16(acc[g * 2 + 1], al, bh1, bh3);
                    }
                }
            }

            // ---- epilogue: thread owns (2 b-rows) x (4 jt) x 4 gate types ----
            const size_t s_cur  = (size_t)cell_id * NB * HID;
            const size_t s_up   = (size_t)(cell_id - HW) * NB * HID;
            const size_t s_left = (size_t)(cell_id - 1) * NB * HID;

            #pragma unroll
            for (int h = 0; h < 2; h++) {
                const int b = m0 + g8 + h * 8;
                const float xp = x[b * (HW * HW) + cell_id];
                #pragma unroll
                for (int p = 0; p < 2; p++) {
                    const int jt0 = p * 8 + q * 2;
                    const int j0e = sb * 16 + jt0;

                    float2 ssum = make_float2(0.f, 0.f);
                    if (has_up) {
                        float2 t = *(const float2*)&g_s[s_up + (size_t)b * HID + j0e];
                        ssum.x += t.x; ssum.y += t.y;
                    }
                    if (has_left) {
                        float2 t = *(const float2*)&g_s[s_left + (size_t)b * HID + j0e];
                        ssum.x += t.x; ssum.y += t.y;
                    }

                    float sv[2], hv[2];
                    #pragma unroll
                    for (int cc = 0; cc < 2; cc++) {
                        const int jt = jt0 + cc;
                        const int e  = h * 2 + cc;
                        const float gi = acc[0 + p][e] + sbias[jt]      + xp * swih[jt];
                        const float gf = acc[2 + p][e] + sbias[16 + jt] + xp * swih[16 + jt];
                        const float gg = acc[4 + p][e] + sbias[32 + jt] + xp * swih[32 + jt];
                        const float go = acc[6 + p][e] + sbias[48 + jt] + xp * swih[48 + jt];

                        const float iv = fsigmoid(gi);
                        const float fv = fsigmoid(gf);
                        const float gv = ftanh(gg);
                        const float ov = fsigmoid(go);

                        const float ss = (cc == 0) ? ssum.x : ssum.y;
                        sv[cc] = fv * ss + iv * gv;
                        hv[cc] = ov * ftanh(sv[cc]);
                    }
                    *(float2*)&g_s[s_cur + (size_t)b * HID + j0e] = make_float2(sv[0], sv[1]);
                    *(float2*)&out[(size_t)b * (HW * HW * HID)
                                   + (size_t)cell_id * HID + j0e]  = make_float2(hv[0], hv[1]);
                }
            }
            __syncthreads();   // all warps done with smem A before next staging
        }
        grid_barrier();
    }
}

extern "C" void kernel_launch(void* const* d_in, const int* in_sizes, int n_in,
                              void* d_out, int out_size) {
    const float* x    = (const float*)d_in[0];
    const float* w_ih = (const float*)d_in[1];
    const float* w_hh = (const float*)d_in[2];
    const float* bias = (const float*)d_in[3];
    float* out = (float*)d_out;

    cudaFuncSetAttribute(mdlstm_mma,
                         cudaFuncAttributeMaxDynamicSharedMemorySize, SMEM_TOTAL);
    mdlstm_mma<<<NBLK, THREADS, SMEM_TOTAL>>>(x, w_ih, w_hh, bias, out);
}

// round 13
// speedup vs baseline: 1.8410x; 1.0523x over previous
#include <cuda_runtime.h>
#include <cuda_bf16.h>
#include <math.h>
#include <stdint.h>

#define HID   256
#define NB    128
#define HW    32
#define NBLK  144            // 9 cell-slots x 16 j-slices, persistent (1/SM)
#define CSLOTS 9
#define THREADS 256
#define PITCH 528            // bytes per bf16 tile row (264 bf16; ldmatrix conflict-free)

// ---- smem layout (bytes) ----
#define SM_CONST 0                              // bias[64], wih[64] floats (512 B)
#define SM_A_HI  1024                           // A hi: 128 x 264 bf16 (67584 B)
#define SM_A_LO  (SM_A_HI + 128 * PITCH)
#define SM_W_HI  (SM_A_LO + 128 * PITCH)        // W hi: 64 x 264 bf16 (33792 B)
#define SM_W_LO  (SM_W_HI + 64 * PITCH)
#define SMEM_TOTAL (SM_W_LO + 64 * PITCH)       // 203776 B

// Cell state s, layout [cell][b][j]. 134 MB scratch.
__device__ float g_s[(size_t)HW * HW * NB * HID];
// grid barrier
__device__ int      g_bar_count;
__device__ unsigned g_bar_gen;

__device__ __forceinline__ uint32_t smem_u32(const void* p) {
    uint32_t a;
    asm("{ .reg .u64 t; cvta.to.shared.u64 t, %1; cvt.u32.u64 %0, t; }" : "=r"(a) : "l"(p));
    return a;
}

// MUFU.TANH-based activations (single-MUFU each).
__device__ __forceinline__ float ftanh(float x) {
    float y;
    asm("tanh.approx.f32 %0, %1;" : "=f"(y) : "f"(x));
    return y;
}
// sigmoid(x) = 0.5*tanh(x/2) + 0.5
__device__ __forceinline__ float fsigmoid(float x) {
    return fmaf(0.5f, ftanh(0.5f * x), 0.5f);
}

__device__ __forceinline__ void ldm_x4(uint32_t& r0, uint32_t& r1, uint32_t& r2, uint32_t& r3,
                                       uint32_t addr) {
    asm volatile("ldmatrix.sync.aligned.m8n8.x4.shared.b16 {%0,%1,%2,%3}, [%4];"
        : "=r"(r0), "=r"(r1), "=r"(r2), "=r"(r3) : "r"(addr));
}
__device__ __forceinline__ void mma_bf16(float* c, const uint32_t* a, uint32_t b0, uint32_t b1) {
    asm volatile(
        "mma.sync.aligned.m16n8k16.row.col.f32.bf16.bf16.f32 "
        "{%0,%1,%2,%3}, {%4,%5,%6,%7}, {%8,%9}, {%0,%1,%2,%3};"
        : "+f"(c[0]), "+f"(c[1]), "+f"(c[2]), "+f"(c[3])
        : "r"(a[0]), "r"(a[1]), "r"(a[2]), "r"(a[3]), "r"(b0), "r"(b1));
}

__device__ __forceinline__ uint32_t bf2u(__nv_bfloat162 v) {
    return *reinterpret_cast<uint32_t*>(&v);
}
// split float pair -> (hi bf16x2, lo bf16x2)
__device__ __forceinline__ void split2(float a, float b, uint32_t& hi, uint32_t& lo) {
    __nv_bfloat162 h = __floats2bfloat162_rn(a, b);
    float la = a - __low2float(h);
    float lb = b - __high2float(h);
    __nv_bfloat162 l = __floats2bfloat162_rn(la, lb);
    hi = bf2u(h); lo = bf2u(l);
}

__device__ __forceinline__ void grid_barrier() {
    __syncthreads();
    if (threadIdx.x == 0) {
        __threadfence();
        unsigned gen = *((volatile unsigned*)&g_bar_gen);
        int t = atomicAdd(&g_bar_count, 1);
        if (t == NBLK - 1) {
            g_bar_count = 0;
            __threadfence();
            atomicAdd(&g_bar_gen, 1u);
        } else {
            while (*((volatile unsigned*)&g_bar_gen) == gen) { }
        }
    }
    __syncthreads();
}

// Persistent MD-LSTM: one launch walks all 63 anti-diagonals.
// Block = 256 threads (8 warps). Tile: M=128 batches x N=64 gate rows
// (n = type*16 + jt; j = sb*16 + jt) x K=256, split-precision bf16 HMMA.
__global__ __launch_bounds__(THREADS, 1)
void mdlstm_mma(const float* __restrict__ x,
                const float* __restrict__ w_ih,
                const float* __restrict__ w_hh,
                const float* __restrict__ bias,
                float*       __restrict__ out)
{
    extern __shared__ unsigned char smem[];
    const uint32_t smb  = smem_u32(smem);
    const int tid  = threadIdx.x;
    const int lane = tid & 31;
    const int wrp  = tid >> 5;            // 0..7
    const int sb    = blockIdx.x & 15;    // j-slice
    const int cslot = blockIdx.x >> 4;    // 0..8

    // ---- one-time: W slice (64 rows x 256 k) split into smem hi/lo ----
    {
        const int n    = tid >> 2;                 // 0..63
        const int kc   = (tid & 3) * 64;
        const int type = n >> 4, jt = n & 15;
        const int j    = sb * 16 + jt;
        const float* src = w_hh + ((size_t)(type * 256 + j) * 256 + kc);
        unsigned char* dhi = smem + SM_W_HI + n * PITCH + kc * 2;
        unsigned char* dlo = smem + SM_W_LO + n * PITCH + kc * 2;
        #pragma unroll 4
        for (int i = 0; i < 16; i++) {
            float4 v = *(const float4*)(src + i * 4);
            uint32_t h0, l0, h1, l1;
            split2(v.x, v.y, h0, l0);
            split2(v.z, v.w, h1, l1);
            *(uint2*)(dhi + i * 8) = make_uint2(h0, h1);
            *(uint2*)(dlo + i * 8) = make_uint2(l0, l1);
        }
    }
    if (tid < 64) {
        const int type = tid >> 4, jt = tid & 15;
        const int j = sb * 16 + jt;
        ((float*)(smem + SM_CONST))[tid]      = bias[type * 256 + j];
        ((float*)(smem + SM_CONST))[64 + tid] = w_ih[type * 256 + j];
    }
    __syncthreads();

    // per-lane ldmatrix address components
    const int m0 = wrp * 16;
    const uint32_t a_off = (uint32_t)(m0 + (lane & 15)) * PITCH + (lane >> 4) * 16;
    const uint32_t b_off = (uint32_t)(lane & 15) * PITCH + (lane >> 4) * 16;

    const int q  = lane & 3;
    const int g8 = lane >> 2;
    const float* sbias = (const float*)(smem + SM_CONST);
    const float* swih  = sbias + 64;

    for (int d = 0; d < 2 * HW - 1; d++) {
        const int n_d = (d < HW) ? (d + 1) : (2 * HW - 1 - d);
        const int r0  = (d > HW - 1) ? d - (HW - 1) : 0;

        for (int cell = cslot; cell < n_d; cell += CSLOTS) {
            const int r = r0 + cell, c = d - r;
            const int cell_id = r * HW + c;
            const bool has_up = (r > 0), has_left = (c > 0);

            float acc[8][4];
            #pragma unroll
            for (int f = 0; f < 8; f++)
                #pragma unroll
                for (int e = 0; e < 4; e++) acc[f][e] = 0.0f;

            if (has_up || has_left) {
                // ---- stage hsum = h_up + h_left, split -> smem A hi/lo ----
                {
                    const int bb = tid >> 1;
                    const int j0 = (tid & 1) * 128;
                    const float* pu = out + (size_t)bb * (HW * HW * HID)
                                          + (size_t)(cell_id - HW) * HID + j0;
                    const float* pl = out + (size_t)bb * (HW * HW * HID)
                                          + (size_t)(cell_id - 1) * HID + j0;
                    unsigned char* ahi = smem + SM_A_HI + bb * PITCH + j0 * 2;
                    unsigned char* alo = smem + SM_A_LO + bb * PITCH + j0 * 2;
                    #pragma unroll 8
                    for (int i = 0; i < 32; i++) {
                        float4 v = make_float4(0.f, 0.f, 0.f, 0.f);
                        if (has_up) {
                            float4 u = *(const float4*)(pu + i * 4);
                            v.x = u.x; v.y = u.y; v.z = u.z; v.w = u.w;
                        }
                        if (has_left) {
                            float4 l = *(const float4*)(pl + i * 4);
                            v.x += l.x; v.y += l.y; v.z += l.z; v.w += l.w;
                        }
                        uint32_t h0, l0, h1, l1;
                        split2(v.x, v.y, h0, l0);
                        split2(v.z, v.w, h1, l1);
                        *(uint2*)(ahi + i * 8) = make_uint2(h0, h1);
                        *(uint2*)(alo + i * 8) = make_uint2(l0, l1);
                    }
                }
                __syncthreads();
            }

            // ---- prefetch epilogue operands (s_up/s_left/x) before GEMM ----
            const size_t s_cur  = (size_t)cell_id * NB * HID;
            const size_t s_up   = (size_t)(cell_id - HW) * NB * HID;
            const size_t s_left = (size_t)(cell_id - 1) * NB * HID;

            float2 pss[2][2];          // [h][p] prefetched s_up+s_left partial sums
            float  pxp[2];             // [h] prefetched x
            #pragma unroll
            for (int h = 0; h < 2; h++) {
                const int b = m0 + g8 + h * 8;
                pxp[h] = x[b * (HW * HW) + cell_id];
                #pragma unroll
                for (int p = 0; p < 2; p++) {
                    const int j0e = sb * 16 + p * 8 + q * 2;
                    float2 ss = make_float2(0.f, 0.f);
                    if (has_up) {
                        float2 t = *(const float2*)&g_s[s_up + (size_t)b * HID + j0e];
                        ss.x += t.x; ss.y += t.y;
                    }
                    if (has_left) {
                        float2 t = *(const float2*)&g_s[s_left + (size_t)b * HID + j0e];
                        ss.x += t.x; ss.y += t.y;
                    }
                    pss[h][p] = ss;
                }
            }

            if (has_up || has_left) {
                // ---- GEMM: gates[b][n] = sum_k hsum[b][k] * W[n][k] ----
                #pragma unroll 2
                for (int kk = 0; kk < 16; kk++) {
                    const uint32_t ka = kk * 32;        // 16 bf16 = 32 B per k-step
                    uint32_t ah[4], al[4];
                    ldm_x4(ah[0], ah[1], ah[2], ah[3], smb + SM_A_HI + a_off + ka);
                    ldm_x4(al[0], al[1], al[2], al[3], smb + SM_A_LO + a_off + ka);
                    #pragma unroll
                    for (int g = 0; g < 4; g++) {
                        uint32_t bh0, bh1, bh2, bh3, bl0, bl1, bl2, bl3;
                        ldm_x4(bh0, bh1, bh2, bh3,
                               smb + SM_W_HI + (uint32_t)g * 16 * PITCH + b_off + ka);
                        ldm_x4(bl0, bl1, bl2, bl3,
                               smb + SM_W_LO + (uint32_t)g * 16 * PITCH + b_off + ka);
                        mma_bf16(acc[g * 2],     ah, bh0, bh2);
                        mma_bf16(acc[g * 2 + 1], ah, bh1, bh3);
                        mma_bf16(acc[g * 2],     ah, bl0, bl2);
                        mma_bf16(acc[g * 2 + 1], ah, bl1, bl3);
                        mma_bf16(acc[g * 2],     al, bh0, bh2);
                        mma_bf16(acc[g * 2 + 1], al, bh1, bh3);
                    }
                }
            }

            // ---- epilogue: thread owns (2 b-rows) x (4 jt) x 4 gate types ----
            #pragma unroll
            for (int h = 0; h < 2; h++) {
                const int b = m0 + g8 + h * 8;
                const float xp = pxp[h];
                #pragma unroll
                for (int p = 0; p < 2; p++) {
                    const int jt0 = p * 8 + q * 2;
                    const int j0e = sb * 16 + jt0;
                    const float2 ssum = pss[h][p];

                    float sv[2], hv[2];
                    #pragma unroll
                    for (int cc = 0; cc < 2; cc++) {
                        const int jt = jt0 + cc;
                        const int e  = h * 2 + cc;
                        const float gi = acc[0 + p][e] + sbias[jt]      + xp * swih[jt];
                        const float gf = acc[2 + p][e] + sbias[16 + jt] + xp * swih[16 + jt];
                        const float gg = acc[4 + p][e] + sbias[32 + jt] + xp * swih[32 + jt];
                        const float go = acc[6 + p][e] + sbias[48 + jt] + xp * swih[48 + jt];

                        const float iv = fsigmoid(gi);
                        const float fv = fsigmoid(gf);
                        const float gv = ftanh(gg);
                        const float ov = fsigmoid(go);

                        const float ss = (cc == 0) ? ssum.x : ssum.y;
                        sv[cc] = fv * ss + iv * gv;
                        hv[cc] = ov * ftanh(sv[cc]);
                    }
                    *(float2*)&g_s[s_cur + (size_t)b * HID + j0e] = make_float2(sv[0], sv[1]);
                    *(float2*)&out[(size_t)b * (HW * HW * HID)
                                   + (size_t)cell_id * HID + j0e]  = make_float2(hv[0], hv[1]);
                }
            }
            __syncthreads();   // all warps done with smem A before next staging
        }
        grid_barrier();
    }
}

extern "C" void kernel_launch(void* const* d_in, const int* in_sizes, int n_in,
                              void* d_out, int out_size) {
    const float* x    = (const float*)d_in[0];
    const float* w_ih = (const float*)d_in[1];
    const float* w_hh = (const float*)d_in[2];
    const float* bias = (const float*)d_in[3];
    float* out = (float*)d_out;

    cudaFuncSetAttribute(mdlstm_mma,
                         cudaFuncAttributeMaxDynamicSharedMemorySize, SMEM_TOTAL);
    mdlstm_mma<<<NBLK, THREADS, SMEM_TOTAL>>>(x, w_ih, w_hh, bias, out);
}